// round 5
// baseline (speedup 1.0000x reference)
#include <cuda_runtime.h>
#include <math.h>
#include <stdint.h>

// ---------------------------------------------------------------------------
// Problem constants
// ---------------------------------------------------------------------------
#define N_NODES 50000
#define E_EDGES 800000
constexpr int EW_BLOCKS = (E_EDGES + 255) / 256;   // 3125

// ---------------------------------------------------------------------------
// Static device scratch
// ---------------------------------------------------------------------------
__device__ __align__(16) float g_h1[N_NODES * 512];
__device__ __align__(16) float g_h2[N_NODES * 64];
__device__ __align__(16) float g_lcat[N_NODES * 128];   // [logits | logits@P]
__device__ __align__(16) float g_hA[N_NODES * 128];
__device__ __align__(16) float g_hB[N_NODES * 128];
__device__ __align__(16) float g_agg[N_NODES * 128];
__device__ __align__(16) float g_Bcat[64 * 128];        // [W3 | W3@P]
__device__ __align__(16) float g_bcat[128];
__device__ float  g_ew[E_EDGES];
__device__ float  g_P[64 * 64];
__device__ float  g_deg[N_NODES];
__device__ float  g_dinv[N_NODES];
__device__ int    g_cnt[N_NODES];
__device__ int    g_ptr[N_NODES + 1];
__device__ int    g_cursor[N_NODES];
__device__ __align__(16) int2 g_ecsr[E_EDGES];
__device__ double g_psum[EW_BLOCKS];
__device__ double g_psq[EW_BLOCKS];
__device__ float  g_ab[2];

// ---------------------------------------------------------------------------
// TF32 helpers
// ---------------------------------------------------------------------------
__device__ __forceinline__ uint32_t f2tf(float v) {
    uint32_t r;
    asm("cvt.rna.tf32.f32 %0, %1;" : "=r"(r) : "f"(v));
    return r;
}
__device__ __forceinline__ void split_tf32(float v, float& hi, float& lo) {
    float hf = __uint_as_float(f2tf(v));
    hi = hf;
    lo = __uint_as_float(f2tf(v - hf));
}

// ---------------------------------------------------------------------------
// Double-buffered TF32 tensor-core GEMM. COMP=true: 3-pass hi/lo compensation.
// C[m,n] = act( alpha*(A@B)[m,n] + bias[n] + gamma*A[m,n] )
// BM=128, BN=64, BK=16; 256 threads; warp tile 32x32 via m16n8k8.
// Requires N%64==0, K%16==0. ADD_SRC requires N==K.
// ---------------------------------------------------------------------------
constexpr int BM = 128, BN = 64, BK = 16;
constexpr int APAD = 20;
constexpr int BPAD = 68;
constexpr int ASZ = BM * APAD;   // per-buffer A floats
constexpr int BSZ = BK * BPAD;   // per-buffer B floats

__device__ __forceinline__ void mma_tf32(float d[4], const uint32_t a[4],
                                         const uint32_t b[2]) {
    asm volatile(
        "mma.sync.aligned.m16n8k8.row.col.f32.tf32.tf32.f32 "
        "{%0,%1,%2,%3}, {%4,%5,%6,%7}, {%8,%9}, {%0,%1,%2,%3};"
        : "+f"(d[0]), "+f"(d[1]), "+f"(d[2]), "+f"(d[3])
        : "r"(a[0]), "r"(a[1]), "r"(a[2]), "r"(a[3]), "r"(b[0]), "r"(b[1]));
}

template<bool RELU, bool ADD_SRC, bool COMP>
__global__ __launch_bounds__(256) void tf32_gemm_kernel(
    const float* __restrict__ A, const float* __restrict__ B,
    const float* __restrict__ bias, float* __restrict__ C,
    int M, int N, int K, float alpha, float gamma)
{
    __shared__ float Ahi[2 * ASZ];
    __shared__ float Bhi[2 * BSZ];
    __shared__ float Alo[COMP ? 2 * ASZ : 1];
    __shared__ float Blo[COMP ? 2 * BSZ : 1];

    const int tid  = threadIdx.x;
    const int lane = tid & 31;
    const int warp = tid >> 5;
    const int wm0  = (warp >> 1) * 32;
    const int wn0  = (warp & 1) * 32;
    const int m0   = blockIdx.x * BM;
    const int n0   = blockIdx.y * BN;

    // staging addresses (constant across iterations)
    const int aRow0 = tid >> 2;                // rows for the 2 A float4s
    const int aC4   = (tid & 3) * 4;
    const int aRow1 = (tid + 256) >> 2;
    const int bRow  = tid >> 4;
    const int bC4   = (tid & 15) * 4;

    float d[2][4][4];
    #pragma unroll
    for (int mt = 0; mt < 2; mt++)
        #pragma unroll
        for (int nt = 0; nt < 4; nt++)
            #pragma unroll
            for (int r = 0; r < 4; r++) d[mt][nt][r] = 0.f;

    const int tr = lane >> 2;
    const int tk = lane & 3;

    float4 aS0, aS1, bS;

    // ---- prefetch tile 0
    {
        aS0 = (m0 + aRow0 < M)
            ? *reinterpret_cast<const float4*>(&A[(size_t)(m0 + aRow0) * K + aC4])
            : make_float4(0.f, 0.f, 0.f, 0.f);
        aS1 = (m0 + aRow1 < M)
            ? *reinterpret_cast<const float4*>(&A[(size_t)(m0 + aRow1) * K + aC4])
            : make_float4(0.f, 0.f, 0.f, 0.f);
        bS  = *reinterpret_cast<const float4*>(&B[(size_t)bRow * N + n0 + bC4]);
    }
    // ---- store tile 0 to buffer 0
    {
        float4 h0, l0, h1, l1, hb, lb;
        if (COMP) {
            split_tf32(aS0.x, h0.x, l0.x); split_tf32(aS0.y, h0.y, l0.y);
            split_tf32(aS0.z, h0.z, l0.z); split_tf32(aS0.w, h0.w, l0.w);
            split_tf32(aS1.x, h1.x, l1.x); split_tf32(aS1.y, h1.y, l1.y);
            split_tf32(aS1.z, h1.z, l1.z); split_tf32(aS1.w, h1.w, l1.w);
            split_tf32(bS.x,  hb.x, lb.x); split_tf32(bS.y,  hb.y, lb.y);
            split_tf32(bS.z,  hb.z, lb.z); split_tf32(bS.w,  hb.w, lb.w);
            *reinterpret_cast<float4*>(&Alo[aRow0 * APAD + aC4]) = l0;
            *reinterpret_cast<float4*>(&Alo[aRow1 * APAD + aC4]) = l1;
            *reinterpret_cast<float4*>(&Blo[bRow * BPAD + bC4])  = lb;
        } else {
            h0.x = __uint_as_float(f2tf(aS0.x)); h0.y = __uint_as_float(f2tf(aS0.y));
            h0.z = __uint_as_float(f2tf(aS0.z)); h0.w = __uint_as_float(f2tf(aS0.w));
            h1.x = __uint_as_float(f2tf(aS1.x)); h1.y = __uint_as_float(f2tf(aS1.y));
            h1.z = __uint_as_float(f2tf(aS1.z)); h1.w = __uint_as_float(f2tf(aS1.w));
            hb.x = __uint_as_float(f2tf(bS.x));  hb.y = __uint_as_float(f2tf(bS.y));
            hb.z = __uint_as_float(f2tf(bS.z));  hb.w = __uint_as_float(f2tf(bS.w));
        }
        *reinterpret_cast<float4*>(&Ahi[aRow0 * APAD + aC4]) = h0;
        *reinterpret_cast<float4*>(&Ahi[aRow1 * APAD + aC4]) = h1;
        *reinterpret_cast<float4*>(&Bhi[bRow * BPAD + bC4])  = hb;
    }
    __syncthreads();

    int cur = 0;
    for (int k0 = 0; k0 < K; k0 += BK) {
        const bool hasNext = (k0 + BK) < K;
        // ---- prefetch next tile into registers
        if (hasNext) {
            const int kn = k0 + BK;
            aS0 = (m0 + aRow0 < M)
                ? *reinterpret_cast<const float4*>(&A[(size_t)(m0 + aRow0) * K + kn + aC4])
                : make_float4(0.f, 0.f, 0.f, 0.f);
            aS1 = (m0 + aRow1 < M)
                ? *reinterpret_cast<const float4*>(&A[(size_t)(m0 + aRow1) * K + kn + aC4])
                : make_float4(0.f, 0.f, 0.f, 0.f);
            bS  = *reinterpret_cast<const float4*>(&B[(size_t)(kn + bRow) * N + n0 + bC4]);
        }

        // ---- compute from buffer cur
        const float* ah_s = &Ahi[cur * ASZ];
        const float* bh_s = &Bhi[cur * BSZ];
        const float* al_s = COMP ? &Alo[cur * ASZ] : nullptr;
        const float* bl_s = COMP ? &Blo[cur * BSZ] : nullptr;
        #pragma unroll
        for (int ks = 0; ks < 2; ks++) {
            const int kb = ks * 8;
            uint32_t ah[2][4], bh[4][2];
            #pragma unroll
            for (int mt = 0; mt < 2; mt++) {
                int r = wm0 + mt * 16 + tr;
                ah[mt][0] = __float_as_uint(ah_s[r * APAD + kb + tk]);
                ah[mt][1] = __float_as_uint(ah_s[(r + 8) * APAD + kb + tk]);
                ah[mt][2] = __float_as_uint(ah_s[r * APAD + kb + tk + 4]);
                ah[mt][3] = __float_as_uint(ah_s[(r + 8) * APAD + kb + tk + 4]);
            }
            #pragma unroll
            for (int nt = 0; nt < 4; nt++) {
                int n = wn0 + nt * 8 + tr;
                bh[nt][0] = __float_as_uint(bh_s[(kb + tk) * BPAD + n]);
                bh[nt][1] = __float_as_uint(bh_s[(kb + 4 + tk) * BPAD + n]);
            }
            if (COMP) {
                uint32_t al[2][4], bl[4][2];
                #pragma unroll
                for (int mt = 0; mt < 2; mt++) {
                    int r = wm0 + mt * 16 + tr;
                    al[mt][0] = __float_as_uint(al_s[r * APAD + kb + tk]);
                    al[mt][1] = __float_as_uint(al_s[(r + 8) * APAD + kb + tk]);
                    al[mt][2] = __float_as_uint(al_s[r * APAD + kb + tk + 4]);
                    al[mt][3] = __float_as_uint(al_s[(r + 8) * APAD + kb + tk + 4]);
                }
                #pragma unroll
                for (int nt = 0; nt < 4; nt++) {
                    int n = wn0 + nt * 8 + tr;
                    bl[nt][0] = __float_as_uint(bl_s[(kb + tk) * BPAD + n]);
                    bl[nt][1] = __float_as_uint(bl_s[(kb + 4 + tk) * BPAD + n]);
                }
                #pragma unroll
                for (int mt = 0; mt < 2; mt++)
                    #pragma unroll
                    for (int nt = 0; nt < 4; nt++) {
                        mma_tf32(d[mt][nt], ah[mt], bh[nt]);
                        mma_tf32(d[mt][nt], ah[mt], bl[nt]);
                        mma_tf32(d[mt][nt], al[mt], bh[nt]);
                    }
            } else {
                #pragma unroll
                for (int mt = 0; mt < 2; mt++)
                    #pragma unroll
                    for (int nt = 0; nt < 4; nt++)
                        mma_tf32(d[mt][nt], ah[mt], bh[nt]);
            }
        }

        // ---- store next tile to alternate buffer
        if (hasNext) {
            const int nb = cur ^ 1;
            float* ahd = &Ahi[nb * ASZ];
            float* bhd = &Bhi[nb * BSZ];
            float4 h0, l0, h1, l1, hb, lb;
            if (COMP) {
                float* ald = &Alo[nb * ASZ];
                float* bld = &Blo[nb * BSZ];
                split_tf32(aS0.x, h0.x, l0.x); split_tf32(aS0.y, h0.y, l0.y);
                split_tf32(aS0.z, h0.z, l0.z); split_tf32(aS0.w, h0.w, l0.w);
                split_tf32(aS1.x, h1.x, l1.x); split_tf32(aS1.y, h1.y, l1.y);
                split_tf32(aS1.z, h1.z, l1.z); split_tf32(aS1.w, h1.w, l1.w);
                split_tf32(bS.x,  hb.x, lb.x); split_tf32(bS.y,  hb.y, lb.y);
                split_tf32(bS.z,  hb.z, lb.z); split_tf32(bS.w,  hb.w, lb.w);
                *reinterpret_cast<float4*>(&ald[aRow0 * APAD + aC4]) = l0;
                *reinterpret_cast<float4*>(&ald[aRow1 * APAD + aC4]) = l1;
                *reinterpret_cast<float4*>(&bld[bRow * BPAD + bC4])  = lb;
            } else {
                h0.x = __uint_as_float(f2tf(aS0.x)); h0.y = __uint_as_float(f2tf(aS0.y));
                h0.z = __uint_as_float(f2tf(aS0.z)); h0.w = __uint_as_float(f2tf(aS0.w));
                h1.x = __uint_as_float(f2tf(aS1.x)); h1.y = __uint_as_float(f2tf(aS1.y));
                h1.z = __uint_as_float(f2tf(aS1.z)); h1.w = __uint_as_float(f2tf(aS1.w));
                hb.x = __uint_as_float(f2tf(bS.x));  hb.y = __uint_as_float(f2tf(bS.y));
                hb.z = __uint_as_float(f2tf(bS.z));  hb.w = __uint_as_float(f2tf(bS.w));
            }
            *reinterpret_cast<float4*>(&ahd[aRow0 * APAD + aC4]) = h0;
            *reinterpret_cast<float4*>(&ahd[aRow1 * APAD + aC4]) = h1;
            *reinterpret_cast<float4*>(&bhd[bRow * BPAD + bC4])  = hb;
            __syncthreads();
            cur = nb;
        }
    }

    // ---- epilogue
    #pragma unroll
    for (int mt = 0; mt < 2; mt++) {
        #pragma unroll
        for (int nt = 0; nt < 4; nt++) {
            int col  = n0 + wn0 + nt * 8 + tk * 2;
            float b0 = 0.f, b1 = 0.f;
            if (bias) { b0 = bias[col]; b1 = bias[col + 1]; }
            #pragma unroll
            for (int half = 0; half < 2; half++) {
                int row = m0 + wm0 + mt * 16 + tr + half * 8;
                if (row < M) {
                    float v0 = alpha * d[mt][nt][half * 2 + 0] + b0;
                    float v1 = alpha * d[mt][nt][half * 2 + 1] + b1;
                    if (ADD_SRC) {
                        float2 s = *reinterpret_cast<const float2*>(&A[(size_t)row * K + col]);
                        v0 += gamma * s.x;
                        v1 += gamma * s.y;
                    }
                    if (RELU) { v0 = fmaxf(v0, 0.f); v1 = fmaxf(v1, 0.f); }
                    *reinterpret_cast<float2*>(&C[(size_t)row * N + col]) = make_float2(v0, v1);
                }
            }
        }
    }
}

// ---------------------------------------------------------------------------
__global__ void relu_p_kernel(const float* __restrict__ parsing)
{
    int i = blockIdx.x * blockDim.x + threadIdx.x;
    if (i < 64 * 64) g_P[i] = fmaxf(2.0f * parsing[i], 0.f);
}

// Bcat = [W3 | W3@P], bcat = [b3 | b3@P]
__global__ void w3p_kernel(const float* __restrict__ w3, const float* __restrict__ b3)
{
    int j = blockIdx.x * blockDim.x + threadIdx.x;
    if (j < 64 * 128) {
        int k = j >> 7;       // 0..63
        int c = j & 127;      // 0..127
        if (c < 64) {
            g_Bcat[j] = w3[k * 64 + c];
        } else {
            int cc = c - 64;
            float s = 0.f;
            #pragma unroll 8
            for (int t = 0; t < 64; t++) s = fmaf(w3[k * 64 + t], g_P[t * 64 + cc], s);
            g_Bcat[j] = s;
        }
    }
    if (blockIdx.x == 0 && threadIdx.x < 128) {
        int c = threadIdx.x;
        float s;
        if (c < 64) s = b3[c];
        else {
            s = 0.f;
            int cc = c - 64;
            for (int t = 0; t < 64; t++) s = fmaf(b3[t], g_P[t * 64 + cc], s);
        }
        g_bcat[c] = s;
    }
}

// ew[e] = dot64(lcat[row][0:64], lcat[col][64:128]), plus block partial sums
__global__ __launch_bounds__(256) void ew_kernel(const int* __restrict__ ei)
{
    int tid = threadIdx.x;
    int e   = blockIdx.x * 256 + tid;
    float v = 0.f;
    if (e < E_EDGES) {
        int r = ei[e];
        int c = ei[E_EDGES + e];
        const float4* lr = reinterpret_cast<const float4*>(g_lcat + (size_t)r * 128);
        const float4* lc = reinterpret_cast<const float4*>(g_lcat + (size_t)c * 128 + 64);
        #pragma unroll
        for (int i = 0; i < 16; i++) {
            float4 a = lr[i], b = lc[i];
            v = fmaf(a.x, b.x, v); v = fmaf(a.y, b.y, v);
            v = fmaf(a.z, b.z, v); v = fmaf(a.w, b.w, v);
        }
        g_ew[e] = v;
    }
    __shared__ double ss[256];
    __shared__ double sq[256];
    ss[tid] = (double)v;
    sq[tid] = (double)v * (double)v;
    __syncthreads();
    #pragma unroll
    for (int s = 128; s > 0; s >>= 1) {
        if (tid < s) { ss[tid] += ss[tid + s]; sq[tid] += sq[tid + s]; }
        __syncthreads();
    }
    if (tid == 0) { g_psum[blockIdx.x] = ss[0]; g_psq[blockIdx.x] = sq[0]; }
}

__global__ __launch_bounds__(256) void stats_kernel()
{
    int tid = threadIdx.x;
    double s = 0.0, q = 0.0;
    for (int i = tid; i < EW_BLOCKS; i += 256) { s += g_psum[i]; q += g_psq[i]; }
    __shared__ double ss[256];
    __shared__ double sq[256];
    ss[tid] = s; sq[tid] = q;
    __syncthreads();
    #pragma unroll
    for (int st = 128; st > 0; st >>= 1) {
        if (tid < st) { ss[tid] += ss[tid + st]; sq[tid] += sq[tid + st]; }
        __syncthreads();
    }
    if (tid == 0) {
        double sum  = ss[0], sumsq = sq[0];
        double mean = sum / (double)E_EDGES;
        double var  = (sumsq - sum * sum / (double)E_EDGES) / (double)(E_EDGES - 1);
        float  a    = sqrtf(1e-4f / (float)var);
        g_ab[0] = a;
        g_ab[1] = 1.0f - a * (float)mean;
    }
}

__global__ void init_deg_cnt_kernel()
{
    int i = blockIdx.x * blockDim.x + threadIdx.x;
    if (i < N_NODES) { g_deg[i] = 1.0f; g_cnt[i] = 0; }
}

__global__ __launch_bounds__(256) void ew_finalize_kernel(const int* __restrict__ ei)
{
    int e = blockIdx.x * blockDim.x + threadIdx.x;
    if (e < E_EDGES) {
        float w = g_ab[0] * g_ew[e] + g_ab[1];
        g_ew[e] = w;
        int c = ei[E_EDGES + e];
        atomicAdd(&g_deg[c], w);
        atomicAdd(&g_cnt[c], 1);
    }
}

__global__ void dinv_kernel()
{
    int i = blockIdx.x * blockDim.x + threadIdx.x;
    if (i < N_NODES) {
        float d = g_deg[i];
        g_dinv[i] = (d > 0.f) ? rsqrtf(d) : 0.f;
    }
}

__global__ __launch_bounds__(1024) void scan_kernel()
{
    __shared__ int partial[1024];
    const int t  = threadIdx.x;
    const int CH = (N_NODES + 1023) / 1024;
    const int base = t * CH;
    int s = 0;
    for (int i = 0; i < CH; i++) {
        int idx = base + i;
        if (idx < N_NODES) s += g_cnt[idx];
    }
    partial[t] = s;
    __syncthreads();
    for (int off = 1; off < 1024; off <<= 1) {
        int v = (t >= off) ? partial[t - off] : 0;
        __syncthreads();
        if (t >= off) partial[t] += v;
        __syncthreads();
    }
    int excl = (t == 0) ? 0 : partial[t - 1];
    for (int i = 0; i < CH; i++) {
        int idx = base + i;
        if (idx < N_NODES) {
            g_ptr[idx]    = excl;
            g_cursor[idx] = excl;
            excl += g_cnt[idx];
        }
    }
    if (t == 0) g_ptr[N_NODES] = E_EDGES;
}

__global__ __launch_bounds__(256) void fill_kernel(const int* __restrict__ ei)
{
    int e = blockIdx.x * blockDim.x + threadIdx.x;
    if (e < E_EDGES) {
        int r = ei[e];
        int c = ei[E_EDGES + e];
        float co = g_dinv[r] * g_ew[e] * g_dinv[c];
        int pos = atomicAdd(&g_cursor[c], 1);
        g_ecsr[pos] = make_int2(r, __float_as_int(co));
    }
}

// warp-per-node gather: agg[i] = dinv[i]^2*hcur[i] + sum_j coef_j * hcur[row_j]
__global__ __launch_bounds__(256) void gather_kernel(const float* __restrict__ hcur)
{
    const int warp = threadIdx.x >> 5;
    const int lane = threadIdx.x & 31;
    const int node = blockIdx.x * 8 + warp;
    if (node >= N_NODES) return;

    float di = g_dinv[node];
    float s  = di * di;
    float4 h = reinterpret_cast<const float4*>(hcur)[(size_t)node * 32 + lane];
    float4 acc = make_float4(s * h.x, s * h.y, s * h.z, s * h.w);

    int j   = g_ptr[node];
    int end = g_ptr[node + 1];
    for (; j + 1 < end; j += 2) {
        int2 e0 = g_ecsr[j];
        int2 e1 = g_ecsr[j + 1];
        float c0 = __int_as_float(e0.y);
        float c1 = __int_as_float(e1.y);
        float4 v0 = reinterpret_cast<const float4*>(hcur)[(size_t)e0.x * 32 + lane];
        float4 v1 = reinterpret_cast<const float4*>(hcur)[(size_t)e1.x * 32 + lane];
        acc.x = fmaf(c0, v0.x, acc.x); acc.y = fmaf(c0, v0.y, acc.y);
        acc.z = fmaf(c0, v0.z, acc.z); acc.w = fmaf(c0, v0.w, acc.w);
        acc.x = fmaf(c1, v1.x, acc.x); acc.y = fmaf(c1, v1.y, acc.y);
        acc.z = fmaf(c1, v1.z, acc.z); acc.w = fmaf(c1, v1.w, acc.w);
    }
    if (j < end) {
        int2 e0 = g_ecsr[j];
        float c0 = __int_as_float(e0.y);
        float4 v0 = reinterpret_cast<const float4*>(hcur)[(size_t)e0.x * 32 + lane];
        acc.x = fmaf(c0, v0.x, acc.x); acc.y = fmaf(c0, v0.y, acc.y);
        acc.z = fmaf(c0, v0.z, acc.z); acc.w = fmaf(c0, v0.w, acc.w);
    }
    reinterpret_cast<float4*>(g_agg)[(size_t)node * 32 + lane] = acc;
}

// ---------------------------------------------------------------------------
// Host launcher
// ---------------------------------------------------------------------------
static void launch_gemm(bool relu, bool add_src, bool comp,
                        const float* A, const float* B, const float* bias, float* C,
                        int M, int N, int K, float alpha, float gamma)
{
    dim3 grid((M + BM - 1) / BM, N / BN);
    if (add_src) {
        tf32_gemm_kernel<true, true, true><<<grid, 256>>>(A, B, bias, C, M, N, K, alpha, gamma);
    } else if (comp) {
        if (relu) tf32_gemm_kernel<true,  false, true><<<grid, 256>>>(A, B, bias, C, M, N, K, alpha, gamma);
        else      tf32_gemm_kernel<false, false, true><<<grid, 256>>>(A, B, bias, C, M, N, K, alpha, gamma);
    } else {
        if (relu) tf32_gemm_kernel<true,  false, false><<<grid, 256>>>(A, B, bias, C, M, N, K, alpha, gamma);
        else      tf32_gemm_kernel<false, false, false><<<grid, 256>>>(A, B, bias, C, M, N, K, alpha, gamma);
    }
}

extern "C" void kernel_launch(void* const* d_in, const int* in_sizes, int n_in,
                              void* d_out, int out_size)
{
    const float* x       = (const float*)d_in[0];
    const int*   ei      = (const int*)  d_in[1];
    const float* mlp_w1  = (const float*)d_in[2];
    const float* mlp_b1  = (const float*)d_in[3];
    const float* mlp_w2  = (const float*)d_in[4];
    const float* mlp_b2  = (const float*)d_in[5];
    const float* mlp_w3  = (const float*)d_in[6];
    const float* mlp_b3  = (const float*)d_in[7];
    const float* parsing = (const float*)d_in[8];
    const float* lin0_w  = (const float*)d_in[9];
    const float* lin0_b  = (const float*)d_in[10];
    const float* lin1_w  = (const float*)d_in[11];
    const float* lin1_b  = (const float*)d_in[12];
    const float* conv_w1 = (const float*)d_in[13];
    float* out = (float*)d_out;

    float *p_h1, *p_h2, *p_lcat, *p_hA, *p_hB, *p_agg, *p_Bcat, *p_bcat;
    cudaGetSymbolAddress((void**)&p_h1,   g_h1);
    cudaGetSymbolAddress((void**)&p_h2,   g_h2);
    cudaGetSymbolAddress((void**)&p_lcat, g_lcat);
    cudaGetSymbolAddress((void**)&p_hA,   g_hA);
    cudaGetSymbolAddress((void**)&p_hB,   g_hB);
    cudaGetSymbolAddress((void**)&p_agg,  g_agg);
    cudaGetSymbolAddress((void**)&p_Bcat, g_Bcat);
    cudaGetSymbolAddress((void**)&p_bcat, g_bcat);

    const int M = N_NODES;
    const float beta0 = (float)log(2.0);
    const float beta1 = (float)log(1.5);

    relu_p_kernel<<<(64 * 64 + 255) / 256, 256>>>(parsing);
    w3p_kernel<<<(64 * 128 + 255) / 256, 256>>>(mlp_w3, mlp_b3);

    // --- MLP edge scorer (single-pass TF32: error absorbed by ew normalization)
    launch_gemm(true,  false, false, x,    mlp_w1, mlp_b1, p_h1,   M, 512, 128, 1.f, 0.f);
    launch_gemm(true,  false, false, p_h1, mlp_w2, mlp_b2, p_h2,   M,  64, 512, 1.f, 0.f);
    launch_gemm(false, false, false, p_h2, p_Bcat, p_bcat, p_lcat, M, 128,  64, 1.f, 0.f);

    // --- x0 = relu(x @ lin0 + b)  (3-pass: feeds output directly)
    launch_gemm(true,  false, true, x, lin0_w, lin0_b, p_hA, M, 128, 128, 1.f, 0.f);

    // --- edge weights + normalization stats + CSR build
    ew_kernel<<<EW_BLOCKS, 256>>>(ei);
    stats_kernel<<<1, 256>>>();
    init_deg_cnt_kernel<<<(N_NODES + 255) / 256, 256>>>();
    ew_finalize_kernel<<<(E_EDGES + 255) / 256, 256>>>(ei);
    dinv_kernel<<<(N_NODES + 255) / 256, 256>>>();
    scan_kernel<<<1, 1024>>>();
    fill_kernel<<<(E_EDGES + 255) / 256, 256>>>(ei);

    // --- GCN2 layer 0
    gather_kernel<<<(N_NODES + 7) / 8, 256>>>(p_hA);
    launch_gemm(true, true, true, p_agg, conv_w1, nullptr, p_hB,
                M, 128, 128, beta0, 1.f - beta0);

    // --- GCN2 layer 1
    gather_kernel<<<(N_NODES + 7) / 8, 256>>>(p_hB);
    launch_gemm(true, true, true, p_agg, conv_w1 + 128 * 128, nullptr, p_hA,
                M, 128, 128, beta1, 1.f - beta1);

    // --- final projection -> d_out
    launch_gemm(false, false, true, p_hA, lin1_w, lin1_b, out, M, 64, 128, 1.f, 0.f);

    (void)in_sizes; (void)n_in; (void)out_size;
}